// round 7
// baseline (speedup 1.0000x reference)
#include <cuda_runtime.h>

// Depthwise 3x3 conv, SAME padding, channel multiplier 2, NHWC fp32.
// x: [16,224,224,96], kernel: [3,3,1,2], bias: [192], out: [16,224,224,192]
// out[b,h,w,c*2+m] = sum_{dh,dw} x[b,h+dh-1,w+dw-1,c] * k[dh,dw,0,m] + bias[c*2+m]
//
// R6: h-streaming. Each thread owns (b, w, channel-pair c2) and walks 56 h rows,
// holding 3 input rows (9 float2) in registers with unroll-3 rotation. Only ONE
// new input row (3 float2) is loaded per output row -> h-load-redundancy gone.
// Thread covers 2 channels x 2 multipliers -> contiguous float4 output store.
// L1 wavefronts/output -31% vs R5 at equal register count / occupancy.

#define BATCH 16
#define HH 224
#define WW 224
#define CIN 96
#define COUT 192
#define HCH 56   // h rows per CTA (224/56 = 4 chunks)

// block: (48, 2) -> 48 channel-pair lanes x 2 w positions
// grid:  (112, 4, 16)
__global__ __launch_bounds__(96, 12) void dwconv_kernel(
    const float* __restrict__ x,
    const float* __restrict__ ker,   // 18 floats [3][3][1][2]
    const float* __restrict__ bias,  // 192 floats
    float* __restrict__ out)
{
    const int c2 = threadIdx.x;                    // 0..47 channel pair
    const int w  = blockIdx.x * 2 + threadIdx.y;   // 0..223
    const int h0 = blockIdx.y * HCH;
    const int b  = blockIdx.z;

    // Weights in registers (R4 lesson: never LDC in the hot loop on sm_103a).
    float kw[3][3][2];
#pragma unroll
    for (int i = 0; i < 3; i++)
#pragma unroll
        for (int j = 0; j < 3; j++)
#pragma unroll
            for (int m = 0; m < 2; m++)
                kw[i][j][m] = __ldg(&ker[(i * 3 + j) * 2 + m]);

    // Thread covers output channels [4*c2, 4*c2+4): {c0m0, c0m1, c1m0, c1m1}
    const float4 bb = *reinterpret_cast<const float4*>(&bias[4 * c2]);

    const bool wlo = (w > 0);
    const bool whi = (w < WW - 1);

    const float* xrow0 = x + (((size_t)b * HH) * WW + w) * CIN + 2 * c2;  // h = 0
    float* orow0 = out + (((size_t)b * HH) * WW + w) * COUT + 4 * c2;

    const float2 z2 = make_float2(0.f, 0.f);

    // Load input row hh into r[0..2] = x at (w-1, w, w+1), zeros out of range.
    auto load_row = [&](float2(&r)[3], int hh) {
        if ((unsigned)hh < (unsigned)HH) {
            const float* p = xrow0 + (size_t)hh * (WW * CIN);
            r[0] = wlo ? *reinterpret_cast<const float2*>(p - CIN) : z2;
            r[1] = *reinterpret_cast<const float2*>(p);
            r[2] = whi ? *reinterpret_cast<const float2*>(p + CIN) : z2;
        } else {
            r[0] = z2; r[1] = z2; r[2] = z2;
        }
    };

    // One output row: load row h+1 into rp, compute out(h) from rm/rz/rp.
    // rp's FMAs go last so rm/rz FMAs (24) cover the fresh load latency.
    auto step = [&](float2(&rm)[3], float2(&rz)[3], float2(&rp)[3], int h) {
        load_row(rp, h + 1);
        float a00 = bb.x, a01 = bb.y, a10 = bb.z, a11 = bb.w;
#pragma unroll
        for (int dw = 0; dw < 3; dw++) {
            const float k0 = kw[0][dw][0], k1 = kw[0][dw][1];
            a00 = fmaf(rm[dw].x, k0, a00); a01 = fmaf(rm[dw].x, k1, a01);
            a10 = fmaf(rm[dw].y, k0, a10); a11 = fmaf(rm[dw].y, k1, a11);
        }
#pragma unroll
        for (int dw = 0; dw < 3; dw++) {
            const float k0 = kw[1][dw][0], k1 = kw[1][dw][1];
            a00 = fmaf(rz[dw].x, k0, a00); a01 = fmaf(rz[dw].x, k1, a01);
            a10 = fmaf(rz[dw].y, k0, a10); a11 = fmaf(rz[dw].y, k1, a11);
        }
#pragma unroll
        for (int dw = 0; dw < 3; dw++) {
            const float k0 = kw[2][dw][0], k1 = kw[2][dw][1];
            a00 = fmaf(rp[dw].x, k0, a00); a01 = fmaf(rp[dw].x, k1, a01);
            a10 = fmaf(rp[dw].y, k0, a10); a11 = fmaf(rp[dw].y, k1, a11);
        }
        *reinterpret_cast<float4*>(orow0 + (size_t)h * (WW * COUT)) =
            make_float4(a00, a01, a10, a11);
    };

    float2 ra[3], rb[3], rc[3];
    load_row(ra, h0 - 1);
    load_row(rb, h0);

    int h = h0;
#pragma unroll 1
    for (int it = 0; it < HCH / 3; ++it) {   // 18 iterations = 54 rows
        step(ra, rb, rc, h); ++h;
        step(rb, rc, ra, h); ++h;
        step(rc, ra, rb, h); ++h;
    }
    step(ra, rb, rc, h); ++h;                // row 54 of chunk
    step(rb, rc, ra, h);                     // row 55 of chunk
}

extern "C" void kernel_launch(void* const* d_in, const int* in_sizes, int n_in,
                              void* d_out, int out_size) {
    const float* x    = (const float*)d_in[0];
    const float* ker  = (const float*)d_in[1];
    const float* bias = (const float*)d_in[2];
    float* out        = (float*)d_out;

    dim3 block(48, 2, 1);
    dim3 grid(WW / 2, HH / HCH, BATCH);
    dwconv_kernel<<<grid, block>>>(x, ker, bias, out);
}

// round 9
// speedup vs baseline: 1.1774x; 1.1774x over previous
#include <cuda_runtime.h>

// Depthwise 3x3 conv, SAME padding, channel multiplier 2, NHWC fp32.
// x: [16,224,224,96], kernel: [3,3,1,2], bias: [192], out: [16,224,224,192]
// out[b,h,w,c*2+m] = sum_{dh,dw} x[b,h+dh-1,w+dw-1,c] * k[dh,dw,0,m] + bias[c*2+m]
//
// R8: R6 h-streaming + DEPTH-2 PREFETCH. 4 input rows held in registers
// (rotation period 4); row h+2 is loaded while output h is computed from
// rows h-1..h+1 -> each load has a full step of slack before first use.
// R6 post-mortem showed minimal traffic but exposed DRAM latency (DRAM
// stuck at 60%, L1/L2 half-idle); this keeps the traffic and hides latency.

#define BATCH 16
#define HH 224
#define WW 224
#define CIN 96
#define COUT 192
#define HCH 56   // h rows per CTA (224/56 = 4 chunks)

// block: (48, 2) -> 48 channel-pair lanes x 2 w positions
// grid:  (112, 4, 16)
__global__ __launch_bounds__(96, 11) void dwconv_kernel(
    const float* __restrict__ x,
    const float* __restrict__ ker,   // 18 floats [3][3][1][2]
    const float* __restrict__ bias,  // 192 floats
    float* __restrict__ out)
{
    const int c2 = threadIdx.x;                    // 0..47 channel pair
    const int w  = blockIdx.x * 2 + threadIdx.y;   // 0..223
    const int h0 = blockIdx.y * HCH;
    const int b  = blockIdx.z;

    // Weights in registers (R4 lesson: never LDC in the hot loop on sm_103a).
    float kw[3][3][2];
#pragma unroll
    for (int i = 0; i < 3; i++)
#pragma unroll
        for (int j = 0; j < 3; j++)
#pragma unroll
            for (int m = 0; m < 2; m++)
                kw[i][j][m] = __ldg(&ker[(i * 3 + j) * 2 + m]);

    // Thread covers output channels [4*c2, 4*c2+4): {c0m0, c0m1, c1m0, c1m1}
    const float4 bb = *reinterpret_cast<const float4*>(&bias[4 * c2]);

    const bool wlo = (w > 0);
    const bool whi = (w < WW - 1);

    const float* xrow0 = x + (((size_t)b * HH) * WW + w) * CIN + 2 * c2;  // h = 0
    float* orow0 = out + (((size_t)b * HH) * WW + w) * COUT + 4 * c2;

    const float2 z2 = make_float2(0.f, 0.f);
    const int hmax = h0 + HCH;   // rows beyond hmax are never consumed

    // Load input row hh into r[0..2] = x at (w-1, w, w+1); zeros out of range.
    auto load_row = [&](float2(&r)[3], int hh) {
        if ((unsigned)hh < (unsigned)HH) {
            const float* p = xrow0 + (size_t)hh * (WW * CIN);
            r[0] = wlo ? *reinterpret_cast<const float2*>(p - CIN) : z2;
            r[1] = *reinterpret_cast<const float2*>(p);
            r[2] = whi ? *reinterpret_cast<const float2*>(p + CIN) : z2;
        } else {
            r[0] = z2; r[1] = z2; r[2] = z2;
        }
    };

    // Output row h from rm/rz/rp (all resident >= 1 full step), while
    // prefetching row h+2 into rn (first used at the END of step h+1).
    auto step = [&](float2(&rm)[3], float2(&rz)[3], float2(&rp)[3],
                    float2(&rn)[3], int h) {
        const int hpre = h + 2;
        load_row(rn, (hpre <= hmax) ? hpre : HH);   // clamp: dead prefetch -> no traffic
        float a00 = bb.x, a01 = bb.y, a10 = bb.z, a11 = bb.w;
#pragma unroll
        for (int dw = 0; dw < 3; dw++) {
            const float k0 = kw[0][dw][0], k1 = kw[0][dw][1];
            a00 = fmaf(rm[dw].x, k0, a00); a01 = fmaf(rm[dw].x, k1, a01);
            a10 = fmaf(rm[dw].y, k0, a10); a11 = fmaf(rm[dw].y, k1, a11);
        }
#pragma unroll
        for (int dw = 0; dw < 3; dw++) {
            const float k0 = kw[1][dw][0], k1 = kw[1][dw][1];
            a00 = fmaf(rz[dw].x, k0, a00); a01 = fmaf(rz[dw].x, k1, a01);
            a10 = fmaf(rz[dw].y, k0, a10); a11 = fmaf(rz[dw].y, k1, a11);
        }
#pragma unroll
        for (int dw = 0; dw < 3; dw++) {
            const float k0 = kw[2][dw][0], k1 = kw[2][dw][1];
            a00 = fmaf(rp[dw].x, k0, a00); a01 = fmaf(rp[dw].x, k1, a01);
            a10 = fmaf(rp[dw].y, k0, a10); a11 = fmaf(rp[dw].y, k1, a11);
        }
        *reinterpret_cast<float4*>(orow0 + (size_t)h * (WW * COUT)) =
            make_float4(a00, a01, a10, a11);
    };

    float2 ra[3], rb[3], rc[3], rd[3];
    load_row(ra, h0 - 1);   // row h0-1
    load_row(rb, h0);       // row h0
    load_row(rc, h0 + 1);   // row h0+1  (depth-2: first step already has slack)

    int h = h0;
#pragma unroll 1
    for (int it = 0; it < HCH / 4; ++it) {   // 14 iterations x 4 rows = 56
        step(ra, rb, rc, rd, h); ++h;        // computes h,   prefetches h+2 -> rd
        step(rb, rc, rd, ra, h); ++h;        //               prefetches h+3 -> ra
        step(rc, rd, ra, rb, h); ++h;
        step(rd, ra, rb, rc, h); ++h;
    }
}

extern "C" void kernel_launch(void* const* d_in, const int* in_sizes, int n_in,
                              void* d_out, int out_size) {
    const float* x    = (const float*)d_in[0];
    const float* ker  = (const float*)d_in[1];
    const float* bias = (const float*)d_in[2];
    float* out        = (float*)d_out;

    dim3 block(48, 2, 1);
    dim3 grid(WW / 2, HH / HCH, BATCH);
    dwconv_kernel<<<grid, block>>>(x, ker, bias, out);
}

// round 10
// speedup vs baseline: 1.2406x; 1.0537x over previous
#include <cuda_runtime.h>

// Depthwise 3x3 conv, SAME padding, channel multiplier 2, NHWC fp32.
// x: [16,224,224,96], kernel: [3,3,1,2], bias: [192], out: [16,224,224,192]
// out[b,h,w,c*2+m] = sum_{dh,dw} x[b,h+dh-1,w+dw-1,c] * k[dh,dw,0,m] + bias[c*2+m]
//
// R10: R8 h-streaming + DEPTH-3 PREFETCH (5 row buffers, rotation period 5).
// Row h+3 is loaded while output h is computed -> 2 full steps of slack per
// load, ~6 loads in flight per warp (Little's law: ~50KB/SM in flight vs
// ~23KB needed to saturate HBM). R8 (depth-2) reached DRAM=70.1%; this
// targets the remaining latency exposure at identical traffic/occupancy.

#define BATCH 16
#define HH 224
#define WW 224
#define CIN 96
#define COUT 192
#define HCH 56   // h rows per CTA (224/56 = 4 chunks)

// block: (48, 2) -> 48 channel-pair lanes x 2 w positions
// grid:  (112, 4, 16)
__global__ __launch_bounds__(96, 11) void dwconv_kernel(
    const float* __restrict__ x,
    const float* __restrict__ ker,   // 18 floats [3][3][1][2]
    const float* __restrict__ bias,  // 192 floats
    float* __restrict__ out)
{
    const int c2 = threadIdx.x;                    // 0..47 channel pair
    const int w  = blockIdx.x * 2 + threadIdx.y;   // 0..223
    const int h0 = blockIdx.y * HCH;
    const int b  = blockIdx.z;

    // Weights in registers (R4 lesson: never LDC in the hot loop on sm_103a).
    float kw[3][3][2];
#pragma unroll
    for (int i = 0; i < 3; i++)
#pragma unroll
        for (int j = 0; j < 3; j++)
#pragma unroll
            for (int m = 0; m < 2; m++)
                kw[i][j][m] = __ldg(&ker[(i * 3 + j) * 2 + m]);

    // Thread covers output channels [4*c2, 4*c2+4): {c0m0, c0m1, c1m0, c1m1}
    const float4 bb = *reinterpret_cast<const float4*>(&bias[4 * c2]);

    const bool wlo = (w > 0);
    const bool whi = (w < WW - 1);

    const float* xrow0 = x + (((size_t)b * HH) * WW + w) * CIN + 2 * c2;  // h = 0
    float* orow0 = out + (((size_t)b * HH) * WW + w) * COUT + 4 * c2;

    const float2 z2 = make_float2(0.f, 0.f);
    const int hmax = h0 + HCH;   // highest row index any compute in this chunk reads

    // Load input row hh into r[0..2] = x at (w-1, w, w+1); zeros out of range.
    auto load_row = [&](float2(&r)[3], int hh) {
        if ((unsigned)hh < (unsigned)HH) {
            const float* p = xrow0 + (size_t)hh * (WW * CIN);
            r[0] = wlo ? *reinterpret_cast<const float2*>(p - CIN) : z2;
            r[1] = *reinterpret_cast<const float2*>(p);
            r[2] = whi ? *reinterpret_cast<const float2*>(p + CIN) : z2;
        } else {
            r[0] = z2; r[1] = z2; r[2] = z2;
        }
    };

    // Output row h from rm/rz/rp (resident >= 2 full steps), while
    // prefetching row h+3 into rn (buffer holding the dead row h-2).
    auto step = [&](float2(&rm)[3], float2(&rz)[3], float2(&rp)[3],
                    float2(&rn)[3], int h) {
        const int hpre = h + 3;
        load_row(rn, (hpre <= hmax) ? hpre : HH);   // clamp: dead prefetch -> no traffic
        float a00 = bb.x, a01 = bb.y, a10 = bb.z, a11 = bb.w;
#pragma unroll
        for (int dw = 0; dw < 3; dw++) {
            const float k0 = kw[0][dw][0], k1 = kw[0][dw][1];
            a00 = fmaf(rm[dw].x, k0, a00); a01 = fmaf(rm[dw].x, k1, a01);
            a10 = fmaf(rm[dw].y, k0, a10); a11 = fmaf(rm[dw].y, k1, a11);
        }
#pragma unroll
        for (int dw = 0; dw < 3; dw++) {
            const float k0 = kw[1][dw][0], k1 = kw[1][dw][1];
            a00 = fmaf(rz[dw].x, k0, a00); a01 = fmaf(rz[dw].x, k1, a01);
            a10 = fmaf(rz[dw].y, k0, a10); a11 = fmaf(rz[dw].y, k1, a11);
        }
#pragma unroll
        for (int dw = 0; dw < 3; dw++) {
            const float k0 = kw[2][dw][0], k1 = kw[2][dw][1];
            a00 = fmaf(rp[dw].x, k0, a00); a01 = fmaf(rp[dw].x, k1, a01);
            a10 = fmaf(rp[dw].y, k0, a10); a11 = fmaf(rp[dw].y, k1, a11);
        }
        *reinterpret_cast<float4*>(orow0 + (size_t)h * (WW * COUT)) =
            make_float4(a00, a01, a10, a11);
    };

    // 5-buffer rotation. Before first step: rows h0-1, h0, h0+1, h0+2 resident.
    float2 r0[3], r1[3], r2[3], r3[3], r4[3];
    load_row(r0, h0 - 1);
    load_row(r1, h0);
    load_row(r2, h0 + 1);
    load_row(r3, h0 + 2);

    int h = h0;
#pragma unroll 1
    for (int it = 0; it < 11; ++it) {        // 11 x 5 = 55 rows
        step(r0, r1, r2, r4, h); ++h;        // computes h, prefetches h+3 -> r4
        step(r1, r2, r3, r0, h); ++h;
        step(r2, r3, r4, r1, h); ++h;
        step(r3, r4, r0, r2, h); ++h;
        step(r4, r0, r1, r3, h); ++h;
    }
    step(r0, r1, r2, r4, h);                 // row 56 of chunk (h0+55)
}

extern "C" void kernel_launch(void* const* d_in, const int* in_sizes, int n_in,
                              void* d_out, int out_size) {
    const float* x    = (const float*)d_in[0];
    const float* ker  = (const float*)d_in[1];
    const float* bias = (const float*)d_in[2];
    float* out        = (float*)d_out;

    dim3 block(48, 2, 1);
    dim3 grid(WW / 2, HH / HCH, BATCH);
    dwconv_kernel<<<grid, block>>>(x, ker, bias, out);
}

// round 11
// speedup vs baseline: 1.2715x; 1.0250x over previous
#include <cuda_runtime.h>

// Depthwise 3x3 conv, SAME padding, channel multiplier 2, NHWC fp32.
// x: [16,224,224,96], kernel: [3,3,1,2], bias: [192], out: [16,224,224,192]
// out[b,h,w,c*2+m] = sum_{dh,dw} x[b,h+dh-1,w+dw-1,c] * k[dh,dw,0,m] + bias[c*2+m]
//
// R11: R10 (h-streaming, depth-3 prefetch, 5-buffer rotation) +
//  (1) 12 CTAs/SM (launch_bounds(96,12), regs 54 fit the 56 cap),
//  (2) running prefetch/store pointers (no per-step IMAD.WIDE chains),
//  (3) 50-step clamp-free main loop + 6-step checked tail
//      (prefetch rows h0+3..h0+52 are provably in-bounds for every chunk).

#define BATCH 16
#define HH 224
#define WW 224
#define CIN 96
#define COUT 192
#define HCH 56   // h rows per CTA (224/56 = 4 chunks)

// block: (48, 2) -> 48 channel-pair lanes x 2 w positions
// grid:  (112, 4, 16)
__global__ __launch_bounds__(96, 12) void dwconv_kernel(
    const float* __restrict__ x,
    const float* __restrict__ ker,   // 18 floats [3][3][1][2]
    const float* __restrict__ bias,  // 192 floats
    float* __restrict__ out)
{
    const int c2 = threadIdx.x;                    // 0..47 channel pair
    const int w  = blockIdx.x * 2 + threadIdx.y;   // 0..223
    const int h0 = blockIdx.y * HCH;
    const int b  = blockIdx.z;

    // Weights in registers (R4 lesson: never LDC in the hot loop on sm_103a).
    float kw[3][3][2];
#pragma unroll
    for (int i = 0; i < 3; i++)
#pragma unroll
        for (int j = 0; j < 3; j++)
#pragma unroll
            for (int m = 0; m < 2; m++)
                kw[i][j][m] = __ldg(&ker[(i * 3 + j) * 2 + m]);

    // Thread covers output channels [4*c2, 4*c2+4): {c0m0, c0m1, c1m0, c1m1}
    const float4 bb = *reinterpret_cast<const float4*>(&bias[4 * c2]);

    const bool wlo = (w > 0);
    const bool whi = (w < WW - 1);

    const size_t xstride = (size_t)WW * CIN;    // floats per input row
    const size_t ostride = (size_t)WW * COUT;   // floats per output row

    const float* xrow0 = x + (((size_t)b * HH) * WW + w) * CIN + 2 * c2;  // h=0
    float* orow0 = out + (((size_t)b * HH) * WW + w) * COUT + 4 * c2;

    const float2 z2 = make_float2(0.f, 0.f);
    const int hmax = h0 + HCH;   // highest row index consumed by this chunk

    // Checked row load (prolog + tail): zeros when hh out of [0, HH).
    auto load_row = [&](float2(&r)[3], int hh) {
        if ((unsigned)hh < (unsigned)HH) {
            const float* p = xrow0 + (size_t)hh * xstride;
            r[0] = wlo ? *reinterpret_cast<const float2*>(p - CIN) : z2;
            r[1] = *reinterpret_cast<const float2*>(p);
            r[2] = whi ? *reinterpret_cast<const float2*>(p + CIN) : z2;
        } else {
            r[0] = z2; r[1] = z2; r[2] = z2;
        }
    };

    // Unchecked row load for the clamp-free main loop (row known in-bounds).
    auto load_row_fast = [&](float2(&r)[3], const float* p) {
        r[0] = wlo ? *reinterpret_cast<const float2*>(p - CIN) : z2;
        r[1] = *reinterpret_cast<const float2*>(p);
        r[2] = whi ? *reinterpret_cast<const float2*>(p + CIN) : z2;
    };

    auto compute = [&](const float2(&rm)[3], const float2(&rz)[3],
                       const float2(&rp)[3], float* po) {
        float a00 = bb.x, a01 = bb.y, a10 = bb.z, a11 = bb.w;
#pragma unroll
        for (int dw = 0; dw < 3; dw++) {
            const float k0 = kw[0][dw][0], k1 = kw[0][dw][1];
            a00 = fmaf(rm[dw].x, k0, a00); a01 = fmaf(rm[dw].x, k1, a01);
            a10 = fmaf(rm[dw].y, k0, a10); a11 = fmaf(rm[dw].y, k1, a11);
        }
#pragma unroll
        for (int dw = 0; dw < 3; dw++) {
            const float k0 = kw[1][dw][0], k1 = kw[1][dw][1];
            a00 = fmaf(rz[dw].x, k0, a00); a01 = fmaf(rz[dw].x, k1, a01);
            a10 = fmaf(rz[dw].y, k0, a10); a11 = fmaf(rz[dw].y, k1, a11);
        }
#pragma unroll
        for (int dw = 0; dw < 3; dw++) {
            const float k0 = kw[2][dw][0], k1 = kw[2][dw][1];
            a00 = fmaf(rp[dw].x, k0, a00); a01 = fmaf(rp[dw].x, k1, a01);
            a10 = fmaf(rp[dw].y, k0, a10); a11 = fmaf(rp[dw].y, k1, a11);
        }
        *reinterpret_cast<float4*>(po) = make_float4(a00, a01, a10, a11);
    };

    // 5-buffer rotation; prolog loads rows h0-1 .. h0+2 (checked: h0-1 may be -1).
    float2 r0[3], r1[3], r2[3], r3[3], r4[3];
    load_row(r0, h0 - 1);
    load_row(r1, h0);
    load_row(r2, h0 + 1);
    load_row(r3, h0 + 2);

    // Main loop: 50 steps (h0 .. h0+49), prefetching rows h0+3 .. h0+52.
    // h0 <= 168 for every chunk -> h0+52 <= 220 < 224: always in-bounds.
    const float* pf = xrow0 + (size_t)(h0 + 3) * xstride;  // next prefetch row
    float* po = orow0 + (size_t)h0 * ostride;              // next store row

    auto step_fast = [&](float2(&rm)[3], float2(&rz)[3], float2(&rp)[3],
                         float2(&rn)[3]) {
        load_row_fast(rn, pf);
        pf += xstride;
        compute(rm, rz, rp, po);
        po += ostride;
    };

#pragma unroll 1
    for (int it = 0; it < 10; ++it) {   // 10 x 5 = 50 rows
        step_fast(r0, r1, r2, r4);
        step_fast(r1, r2, r3, r0);
        step_fast(r2, r3, r4, r1);
        step_fast(r3, r4, r0, r2);
        step_fast(r4, r0, r1, r3);
    }

    // Tail: 6 steps (h0+50 .. h0+55), prefetch clamped (dead rows -> zeros).
    auto step_tail = [&](float2(&rm)[3], float2(&rz)[3], float2(&rp)[3],
                         float2(&rn)[3], int h) {
        const int hpre = h + 3;
        load_row(rn, (hpre <= hmax) ? hpre : HH);  // hh=HH -> zero fill, no traffic
        compute(rm, rz, rp, orow0 + (size_t)h * ostride);
    };

    int h = h0 + 50;
    step_tail(r0, r1, r2, r4, h); ++h;
    step_tail(r1, r2, r3, r0, h); ++h;
    step_tail(r2, r3, r4, r1, h); ++h;
    step_tail(r3, r4, r0, r2, h); ++h;
    step_tail(r4, r0, r1, r3, h); ++h;
    step_tail(r0, r1, r2, r4, h);
}

extern "C" void kernel_launch(void* const* d_in, const int* in_sizes, int n_in,
                              void* d_out, int out_size) {
    const float* x    = (const float*)d_in[0];
    const float* ker  = (const float*)d_in[1];
    const float* bias = (const float*)d_in[2];
    float* out        = (float*)d_out;

    dim3 block(48, 2, 1);
    dim3 grid(WW / 2, HH / HCH, BATCH);
    dwconv_kernel<<<grid, block>>>(x, ker, bias, out);
}